// round 1
// baseline (speedup 1.0000x reference)
#include <cuda_runtime.h>
#include <cstdint>

#define D 128
#define MAXN 100000

// Scratch: m = h @ W_nb^T   (51.2 MB, __device__ global per allocation rules)
__device__ float g_m[(size_t)MAXN * D];
__device__ int g_is64;

// ---------------------------------------------------------------------------
// Detect whether edge index arrays are int64 or int32.
// If int64 (values < 2^31, nonnegative), every odd 32-bit word is zero.
// ---------------------------------------------------------------------------
__global__ void detect_kernel(const int* __restrict__ er) {
    if (threadIdx.x == 0 && blockIdx.x == 0) {
        int f = 1;
#pragma unroll
        for (int i = 1; i < 64; i += 2) f &= (er[i] == 0);
        g_is64 = f;
    }
}

// ---------------------------------------------------------------------------
// Fused dual GEMM:
//   out[r][n] = sum_k h[r][k]*W_self[n][k] + b_self[n] + b_nb[n]
//   g_m[r][n] = sum_k h[r][k]*W_nb[n][k]
// CTA: 64 rows x 128 cols, 256 threads, thread tile 8x4 per matrix.
// ---------------------------------------------------------------------------
__global__ __launch_bounds__(256, 2)
void gemm_dual_kernel(const float* __restrict__ h,
                      const float* __restrict__ Wsf,
                      const float* __restrict__ bsf,
                      const float* __restrict__ Wnb,
                      const float* __restrict__ bnb,
                      float* __restrict__ out,
                      int N) {
    __shared__ float As[16][68];    // A^T chunk: As[k][r], padded (16B-aligned rows)
    __shared__ float W1s[16][132];  // W_self^T chunk: W1s[k][n]
    __shared__ float W2s[16][132];  // W_nb^T   chunk: W2s[k][n]

    const int tid = threadIdx.x;
    const int cg = tid & 31;   // column group: cols cg*4 .. cg*4+3
    const int rg = tid >> 5;   // row group:    rows rg*8 .. rg*8+7
    const int r0 = blockIdx.x * 64;

    float c1[8][4], c2[8][4];
#pragma unroll
    for (int i = 0; i < 8; i++)
#pragma unroll
        for (int j = 0; j < 4; j++) { c1[i][j] = 0.f; c2[i][j] = 0.f; }

    const int lr = tid >> 2;   // 0..63  (row for A load)
    const int lk = tid & 3;    // 0..3   (k-quad for A load)

    for (int k0 = 0; k0 < D; k0 += 16) {
        // ---- global loads (issued before sync so they overlap prior compute)
        float4 av = make_float4(0.f, 0.f, 0.f, 0.f);
        if (r0 + lr < N)
            av = *(const float4*)&h[(size_t)(r0 + lr) * D + k0 + lk * 4];

        float4 w1v[2], w2v[2];
        int nn[2], kk2[2];
#pragma unroll
        for (int i = 0; i < 2; i++) {
            int idx = tid + i * 256;      // 0..511
            nn[i] = idx >> 2;             // 0..127
            kk2[i] = idx & 3;             // 0..3
            w1v[i] = *(const float4*)&Wsf[(size_t)nn[i] * D + k0 + kk2[i] * 4];
            w2v[i] = *(const float4*)&Wnb[(size_t)nn[i] * D + k0 + kk2[i] * 4];
        }

        __syncthreads();   // previous iteration's reads done before overwrite

        As[lk * 4 + 0][lr] = av.x;
        As[lk * 4 + 1][lr] = av.y;
        As[lk * 4 + 2][lr] = av.z;
        As[lk * 4 + 3][lr] = av.w;
#pragma unroll
        for (int i = 0; i < 2; i++) {
            W1s[kk2[i] * 4 + 0][nn[i]] = w1v[i].x;
            W1s[kk2[i] * 4 + 1][nn[i]] = w1v[i].y;
            W1s[kk2[i] * 4 + 2][nn[i]] = w1v[i].z;
            W1s[kk2[i] * 4 + 3][nn[i]] = w1v[i].w;
            W2s[kk2[i] * 4 + 0][nn[i]] = w2v[i].x;
            W2s[kk2[i] * 4 + 1][nn[i]] = w2v[i].y;
            W2s[kk2[i] * 4 + 2][nn[i]] = w2v[i].z;
            W2s[kk2[i] * 4 + 3][nn[i]] = w2v[i].w;
        }
        __syncthreads();

        // ---- compute: 16 k-steps x (8 rows x 4 cols x 2 matrices) FMAs
#pragma unroll
        for (int kk = 0; kk < 16; kk++) {
            float4 a0 = *(const float4*)&As[kk][rg * 8];       // broadcast across warp
            float4 a1 = *(const float4*)&As[kk][rg * 8 + 4];
            float4 w1 = *(const float4*)&W1s[kk][cg * 4];      // conflict-free
            float4 w2 = *(const float4*)&W2s[kk][cg * 4];
            float a[8] = {a0.x, a0.y, a0.z, a0.w, a1.x, a1.y, a1.z, a1.w};
            float b1[4] = {w1.x, w1.y, w1.z, w1.w};
            float b2[4] = {w2.x, w2.y, w2.z, w2.w};
#pragma unroll
            for (int i = 0; i < 8; i++) {
#pragma unroll
                for (int j = 0; j < 4; j++) {
                    c1[i][j] = fmaf(a[i], b1[j], c1[i][j]);
                    c2[i][j] = fmaf(a[i], b2[j], c2[i][j]);
                }
            }
        }
    }

    // ---- epilogue: out gets both biases (b_nb folded in since segsum adds later)
    float4 bsv = *(const float4*)&bsf[cg * 4];
    float4 bnv = *(const float4*)&bnb[cg * 4];
    float bb[4] = {bsv.x + bnv.x, bsv.y + bnv.y, bsv.z + bnv.z, bsv.w + bnv.w};

#pragma unroll
    for (int i = 0; i < 8; i++) {
        int r = r0 + rg * 8 + i;
        if (r < N) {
            float4 o = make_float4(c1[i][0] + bb[0], c1[i][1] + bb[1],
                                   c1[i][2] + bb[2], c1[i][3] + bb[3]);
            *(float4*)&out[(size_t)r * D + cg * 4] = o;
            float4 mm = make_float4(c2[i][0], c2[i][1], c2[i][2], c2[i][3]);
            *(float4*)&g_m[(size_t)r * D + cg * 4] = mm;
        }
    }
}

// ---------------------------------------------------------------------------
// Scatter: out[row] += edge_val[e] * m[col]. One warp per edge, one
// red.global.add.v4.f32 (16B) per lane.
// ---------------------------------------------------------------------------
__global__ void scatter_kernel(const float* __restrict__ ev,
                               const void* __restrict__ er,
                               const void* __restrict__ ec,
                               float* __restrict__ out,
                               int E) {
    const long long e = (long long)blockIdx.x * (blockDim.x >> 5) + (threadIdx.x >> 5);
    const int lane = threadIdx.x & 31;
    if (e >= E) return;

    long long row, col;
    if (g_is64) {
        row = ((const long long*)er)[e];
        col = ((const long long*)ec)[e];
    } else {
        row = (long long)((const int*)er)[e];
        col = (long long)((const int*)ec)[e];
    }
    const float v = __ldg(&ev[e]);

    const float4* m4 = (const float4*)g_m;
    float4 x = m4[col * 32 + lane];
    x.x *= v; x.y *= v; x.z *= v; x.w *= v;

    float4* dst = ((float4*)out) + row * 32 + lane;
    asm volatile("red.global.add.v4.f32 [%0], {%1, %2, %3, %4};"
                 :: "l"(dst), "f"(x.x), "f"(x.y), "f"(x.z), "f"(x.w)
                 : "memory");
}

// ---------------------------------------------------------------------------
extern "C" void kernel_launch(void* const* d_in, const int* in_sizes, int n_in,
                              void* d_out, int out_size) {
    const float* h   = (const float*)d_in[0];
    const float* ev  = (const float*)d_in[1];
    const float* Wsf = (const float*)d_in[2];
    const float* bsf = (const float*)d_in[3];
    const float* Wnb = (const float*)d_in[4];
    const float* bnb = (const float*)d_in[5];
    const void*  er  = d_in[6];
    const void*  ec  = d_in[7];
    float* out = (float*)d_out;

    const int N = in_sizes[0] / D;
    const int E = in_sizes[1];

    detect_kernel<<<1, 32>>>((const int*)er);

    gemm_dual_kernel<<<(N + 63) / 64, 256>>>(h, Wsf, bsf, Wnb, bnb, out, N);

    const int warps_per_block = 8;  // 256 threads
    const int blocks = (int)(((long long)E + warps_per_block - 1) / warps_per_block);
    scatter_kernel<<<blocks, 256>>>(ev, er, ec, out, E);
}

// round 2
// speedup vs baseline: 1.0541x; 1.0541x over previous
#include <cuda_runtime.h>
#include <cstdint>

#define D 128
#define MAXN 100000

// Scratch: m = h @ W_nb^T   (51.2 MB, __device__ global per allocation rules)
__device__ float g_m[(size_t)MAXN * D];

// ---- f32x2 packed-FMA helpers (Blackwell FFMA2 — ptxas never auto-fuses) ----
__device__ __forceinline__ unsigned long long pack2(float x) {
    unsigned long long r;
    asm("mov.b64 %0, {%1, %1};" : "=l"(r) : "f"(x));
    return r;
}
__device__ __forceinline__ void ffma2(unsigned long long& c,
                                      unsigned long long a,
                                      unsigned long long b) {
    asm("fma.rn.f32x2 %0, %1, %2, %0;" : "+l"(c) : "l"(a), "l"(b));
}
__device__ __forceinline__ float2 unpack2(unsigned long long v) {
    float lo, hi;
    asm("mov.b64 {%0, %1}, %2;" : "=f"(lo), "=f"(hi) : "l"(v));
    return make_float2(lo, hi);
}

// ---------------------------------------------------------------------------
// Fused dual GEMM:
//   out[r][n] = sum_k h[r][k]*W_self[n][k] + b_self[n] + b_nb[n]
//   g_m[r][n] = sum_k h[r][k]*W_nb[n][k]
// CTA: 64 rows x 128 cols, 256 threads, thread tile 8x4 per matrix,
// inner product via FFMA2 (2 cols per instruction).
// ---------------------------------------------------------------------------
__global__ __launch_bounds__(256, 2)
void gemm_dual_kernel(const float* __restrict__ h,
                      const float* __restrict__ Wsf,
                      const float* __restrict__ bsf,
                      const float* __restrict__ Wnb,
                      const float* __restrict__ bnb,
                      float* __restrict__ out,
                      int N) {
    __shared__ float As[16][68];    // A^T chunk: As[k][r]   (272B rows, 16B aligned)
    __shared__ float W1s[16][132];  // W_self^T:  W1s[k][n]  (528B rows, 16B aligned)
    __shared__ float W2s[16][132];  // W_nb^T:    W2s[k][n]

    const int tid = threadIdx.x;
    const int cg = tid & 31;   // column group: cols cg*4 .. cg*4+3
    const int rg = tid >> 5;   // row group:    rows rg*8 .. rg*8+7
    const int r0 = blockIdx.x * 64;

    unsigned long long c1[8][2], c2[8][2];   // packed pairs: (col0,col1),(col2,col3)
#pragma unroll
    for (int i = 0; i < 8; i++)
#pragma unroll
        for (int j = 0; j < 2; j++) { c1[i][j] = 0ull; c2[i][j] = 0ull; }

    const int lr = tid >> 2;   // 0..63  (row for A load)
    const int lk = tid & 3;    // 0..3   (k-quad for A load)

    for (int k0 = 0; k0 < D; k0 += 16) {
        // ---- global loads (issued before sync, overlap prior compute)
        float4 av = make_float4(0.f, 0.f, 0.f, 0.f);
        if (r0 + lr < N)
            av = *(const float4*)&h[(size_t)(r0 + lr) * D + k0 + lk * 4];

        float4 w1v[2], w2v[2];
        int nn[2], kk2[2];
#pragma unroll
        for (int i = 0; i < 2; i++) {
            int idx = tid + i * 256;      // 0..511
            nn[i] = idx >> 2;             // 0..127
            kk2[i] = idx & 3;             // 0..3
            w1v[i] = *(const float4*)&Wsf[(size_t)nn[i] * D + k0 + kk2[i] * 4];
            w2v[i] = *(const float4*)&Wnb[(size_t)nn[i] * D + k0 + kk2[i] * 4];
        }

        __syncthreads();   // previous iteration's reads done before overwrite

        As[lk * 4 + 0][lr] = av.x;
        As[lk * 4 + 1][lr] = av.y;
        As[lk * 4 + 2][lr] = av.z;
        As[lk * 4 + 3][lr] = av.w;
#pragma unroll
        for (int i = 0; i < 2; i++) {
            W1s[kk2[i] * 4 + 0][nn[i]] = w1v[i].x;
            W1s[kk2[i] * 4 + 1][nn[i]] = w1v[i].y;
            W1s[kk2[i] * 4 + 2][nn[i]] = w1v[i].z;
            W1s[kk2[i] * 4 + 3][nn[i]] = w1v[i].w;
            W2s[kk2[i] * 4 + 0][nn[i]] = w2v[i].x;
            W2s[kk2[i] * 4 + 1][nn[i]] = w2v[i].y;
            W2s[kk2[i] * 4 + 2][nn[i]] = w2v[i].z;
            W2s[kk2[i] * 4 + 3][nn[i]] = w2v[i].w;
        }
        __syncthreads();

        // ---- compute: 16 k-steps, FFMA2 over packed column pairs
#pragma unroll
        for (int kk = 0; kk < 16; kk++) {
            float4 a0 = *(const float4*)&As[kk][rg * 8];       // warp broadcast
            float4 a1 = *(const float4*)&As[kk][rg * 8 + 4];
            ulonglong2 w1 = *(const ulonglong2*)&W1s[kk][cg * 4];   // conflict-free
            ulonglong2 w2 = *(const ulonglong2*)&W2s[kk][cg * 4];
            float a[8] = {a0.x, a0.y, a0.z, a0.w, a1.x, a1.y, a1.z, a1.w};
#pragma unroll
            for (int i = 0; i < 8; i++) {
                unsigned long long ap = pack2(a[i]);
                ffma2(c1[i][0], ap, w1.x);
                ffma2(c1[i][1], ap, w1.y);
                ffma2(c2[i][0], ap, w2.x);
                ffma2(c2[i][1], ap, w2.y);
            }
        }
    }

    // ---- epilogue: out gets both biases (b_nb folded in since segsum adds later)
    float4 bsv = *(const float4*)&bsf[cg * 4];
    float4 bnv = *(const float4*)&bnb[cg * 4];
    float bb[4] = {bsv.x + bnv.x, bsv.y + bnv.y, bsv.z + bnv.z, bsv.w + bnv.w};

#pragma unroll
    for (int i = 0; i < 8; i++) {
        int r = r0 + rg * 8 + i;
        if (r < N) {
            float2 p0 = unpack2(c1[i][0]);
            float2 p1 = unpack2(c1[i][1]);
            float4 o = make_float4(p0.x + bb[0], p0.y + bb[1],
                                   p1.x + bb[2], p1.y + bb[3]);
            *(float4*)&out[(size_t)r * D + cg * 4] = o;
            float2 q0 = unpack2(c2[i][0]);
            float2 q1 = unpack2(c2[i][1]);
            float4 mm = make_float4(q0.x, q0.y, q1.x, q1.y);
            *(float4*)&g_m[(size_t)r * D + cg * 4] = mm;
        }
    }
}

// ---------------------------------------------------------------------------
// Scatter: out[row] += edge_val[e] * m[col]. One warp per edge, one
// red.global.add.v4.f32 (16B) per lane. int64/int32 index detection is done
// in-warp from the first 64 words of edge_row (all L1-hot).
// ---------------------------------------------------------------------------
__global__ void scatter_kernel(const float* __restrict__ ev,
                               const void* __restrict__ er,
                               const void* __restrict__ ec,
                               float* __restrict__ out,
                               int E) {
    const long long e = (long long)blockIdx.x * (blockDim.x >> 5) + (threadIdx.x >> 5);
    const int lane = threadIdx.x & 31;
    if (e >= E) return;

    // int64 detection: if indices are int64 (<2^31), all odd 32-bit words == 0.
    const int probe = ((const int*)er)[2 * lane + 1];
    const bool is64 = __all_sync(0xFFFFFFFFu, probe == 0);

    long long row, col;
    if (is64) {
        row = ((const long long*)er)[e];
        col = ((const long long*)ec)[e];
    } else {
        row = (long long)((const int*)er)[e];
        col = (long long)((const int*)ec)[e];
    }
    const float v = __ldg(&ev[e]);

    const float4* m4 = (const float4*)g_m;
    float4 x = m4[col * 32 + lane];
    x.x *= v; x.y *= v; x.z *= v; x.w *= v;

    float4* dst = ((float4*)out) + row * 32 + lane;
    asm volatile("red.global.add.v4.f32 [%0], {%1, %2, %3, %4};"
                 :: "l"(dst), "f"(x.x), "f"(x.y), "f"(x.z), "f"(x.w)
                 : "memory");
}

// ---------------------------------------------------------------------------
extern "C" void kernel_launch(void* const* d_in, const int* in_sizes, int n_in,
                              void* d_out, int out_size) {
    const float* h   = (const float*)d_in[0];
    const float* ev  = (const float*)d_in[1];
    const float* Wsf = (const float*)d_in[2];
    const float* bsf = (const float*)d_in[3];
    const float* Wnb = (const float*)d_in[4];
    const float* bnb = (const float*)d_in[5];
    const void*  er  = d_in[6];
    const void*  ec  = d_in[7];
    float* out = (float*)d_out;

    const int N = in_sizes[0] / D;
    const int E = in_sizes[1];

    gemm_dual_kernel<<<(N + 63) / 64, 256>>>(h, Wsf, bsf, Wnb, bnb, out, N);

    const int warps_per_block = 8;  // 256 threads
    const int blocks = (int)(((long long)E + warps_per_block - 1) / warps_per_block);
    scatter_kernel<<<blocks, 256>>>(ev, er, ec, out, E);
}

// round 3
// speedup vs baseline: 1.4304x; 1.3570x over previous
#include <cuda_runtime.h>
#include <cstdint>

#define D 128
#define MAXN 100000
#define MAXE 1600000
#define SCAN_NB ((MAXN + 255) / 256)   // 391

// ---- scratch (__device__ globals per allocation rules) ----
__device__ float g_m[(size_t)MAXN * D];   // m = h @ W_nb^T (51.2 MB)
__device__ int   g_cnt[MAXN];             // per-row edge count
__device__ int   g_rowstart[MAXN];        // CSR row offsets
__device__ int   g_cursor[MAXN];          // fill cursors
__device__ int   g_scol[MAXE];            // CSR col indices (int32)
__device__ float g_sval[MAXE];            // CSR edge values
__device__ int   g_blocksums[SCAN_NB + 1];
__device__ int   g_is64;

// ---- f32x2 packed-FMA helpers (Blackwell FFMA2) ----
__device__ __forceinline__ unsigned long long pack2(float x) {
    unsigned long long r;
    asm("mov.b64 %0, {%1, %1};" : "=l"(r) : "f"(x));
    return r;
}
__device__ __forceinline__ void ffma2(unsigned long long& c,
                                      unsigned long long a,
                                      unsigned long long b) {
    asm("fma.rn.f32x2 %0, %1, %2, %0;" : "+l"(c) : "l"(a), "l"(b));
}
__device__ __forceinline__ float2 unpack2(unsigned long long v) {
    float lo, hi;
    asm("mov.b64 {%0, %1}, %2;" : "=f"(lo), "=f"(hi) : "l"(v));
    return make_float2(lo, hi);
}

// ---------------------------------------------------------------------------
// K0: zero counters + detect int64 vs int32 indices (odd words all zero => i64)
// ---------------------------------------------------------------------------
__global__ void zero_detect_kernel(const int* __restrict__ er, int N) {
    int i = blockIdx.x * blockDim.x + threadIdx.x;
    if (i < N) { g_cnt[i] = 0; g_cursor[i] = 0; }
    if (i == 0) {
        int f = 1;
#pragma unroll
        for (int k = 1; k < 64; k += 2) f &= (er[k] == 0);
        g_is64 = f;
    }
}

// ---------------------------------------------------------------------------
// K1: histogram of edge rows
// ---------------------------------------------------------------------------
__global__ void hist_kernel(const void* __restrict__ er, int E) {
    int e = blockIdx.x * blockDim.x + threadIdx.x;
    if (e >= E) return;
    int row = g_is64 ? (int)((const long long*)er)[e] : ((const int*)er)[e];
    atomicAdd(&g_cnt[row], 1);
}

// ---------------------------------------------------------------------------
// K2a: per-block sums of g_cnt
// ---------------------------------------------------------------------------
__global__ void scan_sums_kernel(int N) {
    __shared__ int sh[256];
    int i = blockIdx.x * 256 + threadIdx.x;
    int v = (i < N) ? g_cnt[i] : 0;
    sh[threadIdx.x] = v;
    __syncthreads();
#pragma unroll
    for (int off = 128; off > 0; off >>= 1) {
        if (threadIdx.x < off) sh[threadIdx.x] += sh[threadIdx.x + off];
        __syncthreads();
    }
    if (threadIdx.x == 0) g_blocksums[blockIdx.x] = sh[0];
}

// ---------------------------------------------------------------------------
// K2b: exclusive scan of block sums (single block, NB <= 512)
// ---------------------------------------------------------------------------
__global__ void scan_top_kernel(int nb) {
    __shared__ int sh[512];
    int t = threadIdx.x;
    int v = (t < nb) ? g_blocksums[t] : 0;
    sh[t] = v;
    __syncthreads();
#pragma unroll
    for (int off = 1; off < 512; off <<= 1) {
        int tmp = (t >= off) ? sh[t - off] : 0;
        __syncthreads();
        sh[t] += tmp;
        __syncthreads();
    }
    if (t < nb) g_blocksums[t] = sh[t] - v;   // exclusive
}

// ---------------------------------------------------------------------------
// K2c: local exclusive scan + block offset -> g_rowstart
// ---------------------------------------------------------------------------
__global__ void scan_local_kernel(int N) {
    __shared__ int sh[256];
    int i = blockIdx.x * 256 + threadIdx.x;
    int t = threadIdx.x;
    int v = (i < N) ? g_cnt[i] : 0;
    sh[t] = v;
    __syncthreads();
#pragma unroll
    for (int off = 1; off < 256; off <<= 1) {
        int tmp = (t >= off) ? sh[t - off] : 0;
        __syncthreads();
        sh[t] += tmp;
        __syncthreads();
    }
    if (i < N) g_rowstart[i] = sh[t] - v + g_blocksums[blockIdx.x];
}

// ---------------------------------------------------------------------------
// K3: bucket edges into CSR order
// ---------------------------------------------------------------------------
__global__ void bucket_kernel(const float* __restrict__ ev,
                              const void* __restrict__ er,
                              const void* __restrict__ ec,
                              int E) {
    int e = blockIdx.x * blockDim.x + threadIdx.x;
    if (e >= E) return;
    int row, col;
    if (g_is64) {
        row = (int)((const long long*)er)[e];
        col = (int)((const long long*)ec)[e];
    } else {
        row = ((const int*)er)[e];
        col = ((const int*)ec)[e];
    }
    int pos = g_rowstart[row] + atomicAdd(&g_cursor[row], 1);
    g_scol[pos] = col;
    g_sval[pos] = ev[e];
}

// ---------------------------------------------------------------------------
// Fused dual GEMM (unchanged from R2):
//   out[r][n] = h@W_self^T + b_self + b_nb ;  g_m[r][n] = h@W_nb^T
// ---------------------------------------------------------------------------
__global__ __launch_bounds__(256, 2)
void gemm_dual_kernel(const float* __restrict__ h,
                      const float* __restrict__ Wsf,
                      const float* __restrict__ bsf,
                      const float* __restrict__ Wnb,
                      const float* __restrict__ bnb,
                      float* __restrict__ out,
                      int N) {
    __shared__ float As[16][68];
    __shared__ float W1s[16][132];
    __shared__ float W2s[16][132];

    const int tid = threadIdx.x;
    const int cg = tid & 31;
    const int rg = tid >> 5;
    const int r0 = blockIdx.x * 64;

    unsigned long long c1[8][2], c2[8][2];
#pragma unroll
    for (int i = 0; i < 8; i++)
#pragma unroll
        for (int j = 0; j < 2; j++) { c1[i][j] = 0ull; c2[i][j] = 0ull; }

    const int lr = tid >> 2;
    const int lk = tid & 3;

    for (int k0 = 0; k0 < D; k0 += 16) {
        float4 av = make_float4(0.f, 0.f, 0.f, 0.f);
        if (r0 + lr < N)
            av = *(const float4*)&h[(size_t)(r0 + lr) * D + k0 + lk * 4];

        float4 w1v[2], w2v[2];
        int nn[2], kk2[2];
#pragma unroll
        for (int i = 0; i < 2; i++) {
            int idx = tid + i * 256;
            nn[i] = idx >> 2;
            kk2[i] = idx & 3;
            w1v[i] = *(const float4*)&Wsf[(size_t)nn[i] * D + k0 + kk2[i] * 4];
            w2v[i] = *(const float4*)&Wnb[(size_t)nn[i] * D + k0 + kk2[i] * 4];
        }

        __syncthreads();

        As[lk * 4 + 0][lr] = av.x;
        As[lk * 4 + 1][lr] = av.y;
        As[lk * 4 + 2][lr] = av.z;
        As[lk * 4 + 3][lr] = av.w;
#pragma unroll
        for (int i = 0; i < 2; i++) {
            W1s[kk2[i] * 4 + 0][nn[i]] = w1v[i].x;
            W1s[kk2[i] * 4 + 1][nn[i]] = w1v[i].y;
            W1s[kk2[i] * 4 + 2][nn[i]] = w1v[i].z;
            W1s[kk2[i] * 4 + 3][nn[i]] = w1v[i].w;
            W2s[kk2[i] * 4 + 0][nn[i]] = w2v[i].x;
            W2s[kk2[i] * 4 + 1][nn[i]] = w2v[i].y;
            W2s[kk2[i] * 4 + 2][nn[i]] = w2v[i].z;
            W2s[kk2[i] * 4 + 3][nn[i]] = w2v[i].w;
        }
        __syncthreads();

#pragma unroll
        for (int kk = 0; kk < 16; kk++) {
            float4 a0 = *(const float4*)&As[kk][rg * 8];
            float4 a1 = *(const float4*)&As[kk][rg * 8 + 4];
            ulonglong2 w1 = *(const ulonglong2*)&W1s[kk][cg * 4];
            ulonglong2 w2 = *(const ulonglong2*)&W2s[kk][cg * 4];
            float a[8] = {a0.x, a0.y, a0.z, a0.w, a1.x, a1.y, a1.z, a1.w};
#pragma unroll
            for (int i = 0; i < 8; i++) {
                unsigned long long ap = pack2(a[i]);
                ffma2(c1[i][0], ap, w1.x);
                ffma2(c1[i][1], ap, w1.y);
                ffma2(c2[i][0], ap, w2.x);
                ffma2(c2[i][1], ap, w2.y);
            }
        }
    }

    float4 bsv = *(const float4*)&bsf[cg * 4];
    float4 bnv = *(const float4*)&bnb[cg * 4];
    float bb[4] = {bsv.x + bnv.x, bsv.y + bnv.y, bsv.z + bnv.z, bsv.w + bnv.w};

#pragma unroll
    for (int i = 0; i < 8; i++) {
        int r = r0 + rg * 8 + i;
        if (r < N) {
            float2 p0 = unpack2(c1[i][0]);
            float2 p1 = unpack2(c1[i][1]);
            *(float4*)&out[(size_t)r * D + cg * 4] =
                make_float4(p0.x + bb[0], p0.y + bb[1], p1.x + bb[2], p1.y + bb[3]);
            float2 q0 = unpack2(c2[i][0]);
            float2 q1 = unpack2(c2[i][1]);
            *(float4*)&g_m[(size_t)r * D + cg * 4] =
                make_float4(q0.x, q0.y, q1.x, q1.y);
        }
    }
}

// ---------------------------------------------------------------------------
// K4: aggregation. One warp owns one row: out[row] += sum_e val_e * m[col_e].
// Register accumulation, no atomics, single sequential out RMW.
// ---------------------------------------------------------------------------
__global__ __launch_bounds__(256)
void aggregate_kernel(float* __restrict__ out, int N) {
    const int warp = threadIdx.x >> 5;
    const int lane = threadIdx.x & 31;
    const int r = blockIdx.x * 8 + warp;
    if (r >= N) return;

    const int start = g_rowstart[r];
    const int cnt = g_cnt[r];
    if (cnt == 0) return;

    const float4* __restrict__ m4 = (const float4*)g_m;
    float4 acc = make_float4(0.f, 0.f, 0.f, 0.f);

    int i = 0;
    for (; i + 2 <= cnt; i += 2) {
        int c0 = g_scol[start + i];
        int c1 = g_scol[start + i + 1];
        float v0 = g_sval[start + i];
        float v1 = g_sval[start + i + 1];
        float4 x0 = m4[(size_t)c0 * 32 + lane];
        float4 x1 = m4[(size_t)c1 * 32 + lane];
        acc.x = fmaf(v0, x0.x, acc.x); acc.y = fmaf(v0, x0.y, acc.y);
        acc.z = fmaf(v0, x0.z, acc.z); acc.w = fmaf(v0, x0.w, acc.w);
        acc.x = fmaf(v1, x1.x, acc.x); acc.y = fmaf(v1, x1.y, acc.y);
        acc.z = fmaf(v1, x1.z, acc.z); acc.w = fmaf(v1, x1.w, acc.w);
    }
    if (i < cnt) {
        int c0 = g_scol[start + i];
        float v0 = g_sval[start + i];
        float4 x0 = m4[(size_t)c0 * 32 + lane];
        acc.x = fmaf(v0, x0.x, acc.x); acc.y = fmaf(v0, x0.y, acc.y);
        acc.z = fmaf(v0, x0.z, acc.z); acc.w = fmaf(v0, x0.w, acc.w);
    }

    float4* op = (float4*)out + (size_t)r * 32 + lane;
    float4 o = *op;
    o.x += acc.x; o.y += acc.y; o.z += acc.z; o.w += acc.w;
    *op = o;
}

// ---------------------------------------------------------------------------
extern "C" void kernel_launch(void* const* d_in, const int* in_sizes, int n_in,
                              void* d_out, int out_size) {
    const float* h   = (const float*)d_in[0];
    const float* ev  = (const float*)d_in[1];
    const float* Wsf = (const float*)d_in[2];
    const float* bsf = (const float*)d_in[3];
    const float* Wnb = (const float*)d_in[4];
    const float* bnb = (const float*)d_in[5];
    const void*  er  = d_in[6];
    const void*  ec  = d_in[7];
    float* out = (float*)d_out;

    const int N = in_sizes[0] / D;
    const int E = in_sizes[1];
    const int nbN = (N + 255) / 256;
    const int nbE = (E + 255) / 256;

    zero_detect_kernel<<<nbN, 256>>>((const int*)er, N);
    hist_kernel<<<nbE, 256>>>(er, E);
    scan_sums_kernel<<<nbN, 256>>>(N);
    scan_top_kernel<<<1, 512>>>(nbN);
    scan_local_kernel<<<nbN, 256>>>(N);
    bucket_kernel<<<nbE, 256>>>(ev, er, ec, E);

    gemm_dual_kernel<<<(N + 63) / 64, 256>>>(h, Wsf, bsf, Wnb, bnb, out, N);

    aggregate_kernel<<<(N + 7) / 8, 256>>>(out, N);
}

// round 4
// speedup vs baseline: 1.5563x; 1.0880x over previous
#include <cuda_runtime.h>
#include <cuda_fp16.h>
#include <cstdint>

#define D 128
#define MAXN 100000
#define MAXE 1600000
#define SCAN_NB ((MAXN + 255) / 256)   // 391

// ---- scratch (__device__ globals per allocation rules) ----
__device__ __half g_mh[(size_t)MAXN * D];  // m = h @ W_nb^T in fp16 (25.6 MB)
__device__ int   g_cnt[MAXN];
__device__ int   g_rowstart[MAXN];
__device__ int   g_cursor[MAXN];
__device__ int   g_scol[MAXE];
__device__ float g_sval[MAXE];
__device__ int   g_blocksums[SCAN_NB + 1];
__device__ int   g_is64;

// ---- f32x2 packed-FMA helpers (Blackwell FFMA2) ----
__device__ __forceinline__ unsigned long long pack2(float x) {
    unsigned long long r;
    asm("mov.b64 %0, {%1, %1};" : "=l"(r) : "f"(x));
    return r;
}
__device__ __forceinline__ void ffma2(unsigned long long& c,
                                      unsigned long long a,
                                      unsigned long long b) {
    asm("fma.rn.f32x2 %0, %1, %2, %0;" : "+l"(c) : "l"(a), "l"(b));
}
__device__ __forceinline__ float2 unpack2(unsigned long long v) {
    float lo, hi;
    asm("mov.b64 {%0, %1}, %2;" : "=f"(lo), "=f"(hi) : "l"(v));
    return make_float2(lo, hi);
}

// ---------------------------------------------------------------------------
// K0: zero counters + detect int64 vs int32 indices
// ---------------------------------------------------------------------------
__global__ void zero_detect_kernel(const int* __restrict__ er, int N) {
    int i = blockIdx.x * blockDim.x + threadIdx.x;
    if (i < N) { g_cnt[i] = 0; g_cursor[i] = 0; }
    if (i == 0) {
        int f = 1;
#pragma unroll
        for (int k = 1; k < 64; k += 2) f &= (er[k] == 0);
        g_is64 = f;
    }
}

__global__ void hist_kernel(const void* __restrict__ er, int E) {
    int e = blockIdx.x * blockDim.x + threadIdx.x;
    if (e >= E) return;
    int row = g_is64 ? (int)((const long long*)er)[e] : ((const int*)er)[e];
    atomicAdd(&g_cnt[row], 1);
}

__global__ void scan_sums_kernel(int N) {
    __shared__ int sh[256];
    int i = blockIdx.x * 256 + threadIdx.x;
    int v = (i < N) ? g_cnt[i] : 0;
    sh[threadIdx.x] = v;
    __syncthreads();
#pragma unroll
    for (int off = 128; off > 0; off >>= 1) {
        if (threadIdx.x < off) sh[threadIdx.x] += sh[threadIdx.x + off];
        __syncthreads();
    }
    if (threadIdx.x == 0) g_blocksums[blockIdx.x] = sh[0];
}

__global__ void scan_top_kernel(int nb) {
    __shared__ int sh[512];
    int t = threadIdx.x;
    int v = (t < nb) ? g_blocksums[t] : 0;
    sh[t] = v;
    __syncthreads();
#pragma unroll
    for (int off = 1; off < 512; off <<= 1) {
        int tmp = (t >= off) ? sh[t - off] : 0;
        __syncthreads();
        sh[t] += tmp;
        __syncthreads();
    }
    if (t < nb) g_blocksums[t] = sh[t] - v;   // exclusive
}

__global__ void scan_local_kernel(int N) {
    __shared__ int sh[256];
    int i = blockIdx.x * 256 + threadIdx.x;
    int t = threadIdx.x;
    int v = (i < N) ? g_cnt[i] : 0;
    sh[t] = v;
    __syncthreads();
#pragma unroll
    for (int off = 1; off < 256; off <<= 1) {
        int tmp = (t >= off) ? sh[t - off] : 0;
        __syncthreads();
        sh[t] += tmp;
        __syncthreads();
    }
    if (i < N) g_rowstart[i] = sh[t] - v + g_blocksums[blockIdx.x];
}

__global__ void bucket_kernel(const float* __restrict__ ev,
                              const void* __restrict__ er,
                              const void* __restrict__ ec,
                              int E) {
    int e = blockIdx.x * blockDim.x + threadIdx.x;
    if (e >= E) return;
    int row, col;
    if (g_is64) {
        row = (int)((const long long*)er)[e];
        col = (int)((const long long*)ec)[e];
    } else {
        row = ((const int*)er)[e];
        col = ((const int*)ec)[e];
    }
    int pos = g_rowstart[row] + atomicAdd(&g_cursor[row], 1);
    g_scol[pos] = col;
    g_sval[pos] = ev[e];
}

// ---------------------------------------------------------------------------
// Fused dual GEMM, double-buffered smem pipeline:
//   out[r][n] = h@W_self^T + b_self + b_nb ;  g_mh[r][n] = fp16(h@W_nb^T)
// ---------------------------------------------------------------------------
#define GEMM_LOAD(K0)                                                          \
    do {                                                                       \
        av = make_float4(0.f, 0.f, 0.f, 0.f);                                  \
        if (r0 + lr < N)                                                       \
            av = *(const float4*)&h[(size_t)(r0 + lr) * D + (K0) + lk * 4];    \
        _Pragma("unroll")                                                      \
        for (int i = 0; i < 2; i++) {                                          \
            w1v[i] = *(const float4*)&Wsf[(size_t)nn[i] * D + (K0) + kk2[i] * 4]; \
            w2v[i] = *(const float4*)&Wnb[(size_t)nn[i] * D + (K0) + kk2[i] * 4]; \
        }                                                                      \
    } while (0)

#define GEMM_STS(S)                                                            \
    do {                                                                       \
        As[S][lk * 4 + 0][lr] = av.x;                                          \
        As[S][lk * 4 + 1][lr] = av.y;                                          \
        As[S][lk * 4 + 2][lr] = av.z;                                          \
        As[S][lk * 4 + 3][lr] = av.w;                                          \
        _Pragma("unroll")                                                      \
        for (int i = 0; i < 2; i++) {                                          \
            W1s[S][kk2[i] * 4 + 0][nn[i]] = w1v[i].x;                          \
            W1s[S][kk2[i] * 4 + 1][nn[i]] = w1v[i].y;                          \
            W1s[S][kk2[i] * 4 + 2][nn[i]] = w1v[i].z;                          \
            W1s[S][kk2[i] * 4 + 3][nn[i]] = w1v[i].w;                          \
            W2s[S][kk2[i] * 4 + 0][nn[i]] = w2v[i].x;                          \
            W2s[S][kk2[i] * 4 + 1][nn[i]] = w2v[i].y;                          \
            W2s[S][kk2[i] * 4 + 2][nn[i]] = w2v[i].z;                          \
            W2s[S][kk2[i] * 4 + 3][nn[i]] = w2v[i].w;                          \
        }                                                                      \
    } while (0)

__global__ __launch_bounds__(256, 2)
void gemm_dual_kernel(const float* __restrict__ h,
                      const float* __restrict__ Wsf,
                      const float* __restrict__ bsf,
                      const float* __restrict__ Wnb,
                      const float* __restrict__ bnb,
                      float* __restrict__ out,
                      int N) {
    __shared__ float As[2][16][68];
    __shared__ float W1s[2][16][132];
    __shared__ float W2s[2][16][132];

    const int tid = threadIdx.x;
    const int cg = tid & 31;
    const int rg = tid >> 5;
    const int r0 = blockIdx.x * 64;

    unsigned long long c1[8][2], c2[8][2];
#pragma unroll
    for (int i = 0; i < 8; i++)
#pragma unroll
        for (int j = 0; j < 2; j++) { c1[i][j] = 0ull; c2[i][j] = 0ull; }

    const int lr = tid >> 2;
    const int lk = tid & 3;
    int nn[2], kk2[2];
#pragma unroll
    for (int i = 0; i < 2; i++) {
        int idx = tid + i * 256;
        nn[i] = idx >> 2;
        kk2[i] = idx & 3;
    }

    float4 av, w1v[2], w2v[2];

    // prologue: stage 0
    GEMM_LOAD(0);
    GEMM_STS(0);
    __syncthreads();

#pragma unroll
    for (int it = 0; it < 8; it++) {
        const int cur = it & 1;
        if (it < 7) GEMM_LOAD((it + 1) * 16);   // prefetch next stage

        // ---- compute on buf[cur]
#pragma unroll
        for (int kk = 0; kk < 16; kk++) {
            float4 a0 = *(const float4*)&As[cur][kk][rg * 8];
            float4 a1 = *(const float4*)&As[cur][kk][rg * 8 + 4];
            ulonglong2 w1 = *(const ulonglong2*)&W1s[cur][kk][cg * 4];
            ulonglong2 w2 = *(const ulonglong2*)&W2s[cur][kk][cg * 4];
            float a[8] = {a0.x, a0.y, a0.z, a0.w, a1.x, a1.y, a1.z, a1.w};
#pragma unroll
            for (int i = 0; i < 8; i++) {
                unsigned long long ap = pack2(a[i]);
                ffma2(c1[i][0], ap, w1.x);
                ffma2(c1[i][1], ap, w1.y);
                ffma2(c2[i][0], ap, w2.x);
                ffma2(c2[i][1], ap, w2.y);
            }
        }

        if (it < 7) {
            __syncthreads();          // all warps done reading buf[cur^1] (it-1)
            GEMM_STS(cur ^ 1);
            __syncthreads();          // stage visible before next compute
        }
    }

    // ---- epilogue
    float4 bsv = *(const float4*)&bsf[cg * 4];
    float4 bnv = *(const float4*)&bnb[cg * 4];
    float bb[4] = {bsv.x + bnv.x, bsv.y + bnv.y, bsv.z + bnv.z, bsv.w + bnv.w};

#pragma unroll
    for (int i = 0; i < 8; i++) {
        int r = r0 + rg * 8 + i;
        if (r < N) {
            float2 p0 = unpack2(c1[i][0]);
            float2 p1 = unpack2(c1[i][1]);
            *(float4*)&out[(size_t)r * D + cg * 4] =
                make_float4(p0.x + bb[0], p0.y + bb[1], p1.x + bb[2], p1.y + bb[3]);
            float2 q0 = unpack2(c2[i][0]);
            float2 q1 = unpack2(c2[i][1]);
            union { __half2 h2[2]; uint2 u; } uu;
            uu.h2[0] = __floats2half2_rn(q0.x, q0.y);
            uu.h2[1] = __floats2half2_rn(q1.x, q1.y);
            *(uint2*)&g_mh[(size_t)r * D + cg * 4] = uu.u;
        }
    }
}

// ---------------------------------------------------------------------------
// K4: aggregation over fp16 m. One warp per row, fp32 register accumulation.
// ---------------------------------------------------------------------------
__global__ __launch_bounds__(256)
void aggregate_kernel(float* __restrict__ out, int N) {
    const int warp = threadIdx.x >> 5;
    const int lane = threadIdx.x & 31;
    const int r = blockIdx.x * 8 + warp;
    if (r >= N) return;

    const int start = g_rowstart[r];
    const int cnt = g_cnt[r];
    if (cnt == 0) return;

    const uint2* __restrict__ m2 = (const uint2*)g_mh;
    float4 acc = make_float4(0.f, 0.f, 0.f, 0.f);

    int i = 0;
    for (; i + 2 <= cnt; i += 2) {
        int c0 = g_scol[start + i];
        int c1 = g_scol[start + i + 1];
        float v0 = g_sval[start + i];
        float v1 = g_sval[start + i + 1];
        uint2 r0 = m2[(size_t)c0 * 32 + lane];
        uint2 r1 = m2[(size_t)c1 * 32 + lane];
        float2 f00 = __half22float2(*(__half2*)&r0.x);
        float2 f01 = __half22float2(*(__half2*)&r0.y);
        float2 f10 = __half22float2(*(__half2*)&r1.x);
        float2 f11 = __half22float2(*(__half2*)&r1.y);
        acc.x = fmaf(v0, f00.x, acc.x); acc.y = fmaf(v0, f00.y, acc.y);
        acc.z = fmaf(v0, f01.x, acc.z); acc.w = fmaf(v0, f01.y, acc.w);
        acc.x = fmaf(v1, f10.x, acc.x); acc.y = fmaf(v1, f10.y, acc.y);
        acc.z = fmaf(v1, f11.x, acc.z); acc.w = fmaf(v1, f11.y, acc.w);
    }
    if (i < cnt) {
        int c0 = g_scol[start + i];
        float v0 = g_sval[start + i];
        uint2 r0 = m2[(size_t)c0 * 32 + lane];
        float2 f00 = __half22float2(*(__half2*)&r0.x);
        float2 f01 = __half22float2(*(__half2*)&r0.y);
        acc.x = fmaf(v0, f00.x, acc.x); acc.y = fmaf(v0, f00.y, acc.y);
        acc.z = fmaf(v0, f01.x, acc.z); acc.w = fmaf(v0, f01.y, acc.w);
    }

    float4* op = (float4*)out + (size_t)r * 32 + lane;
    float4 o = *op;
    o.x += acc.x; o.y += acc.y; o.z += acc.z; o.w += acc.w;
    *op = o;
}

// ---------------------------------------------------------------------------
extern "C" void kernel_launch(void* const* d_in, const int* in_sizes, int n_in,
                              void* d_out, int out_size) {
    const float* h   = (const float*)d_in[0];
    const float* ev  = (const float*)d_in[1];
    const float* Wsf = (const float*)d_in[2];
    const float* bsf = (const float*)d_in[3];
    const float* Wnb = (const float*)d_in[4];
    const float* bnb = (const float*)d_in[5];
    const void*  er  = d_in[6];
    const void*  ec  = d_in[7];
    float* out = (float*)d_out;

    const int N = in_sizes[0] / D;
    const int E = in_sizes[1];
    const int nbN = (N + 255) / 256;
    const int nbE = (E + 255) / 256;

    zero_detect_kernel<<<nbN, 256>>>((const int*)er, N);
    hist_kernel<<<nbE, 256>>>(er, E);
    scan_sums_kernel<<<nbN, 256>>>(N);
    scan_top_kernel<<<1, 512>>>(nbN);
    scan_local_kernel<<<nbN, 256>>>(N);
    bucket_kernel<<<nbE, 256>>>(ev, er, ec, E);

    gemm_dual_kernel<<<(N + 63) / 64, 256>>>(h, Wsf, bsf, Wnb, bnb, out, N);

    aggregate_kernel<<<(N + 7) / 8, 256>>>(out, N);
}